// round 1
// baseline (speedup 1.0000x reference)
#include <cuda_runtime.h>
#include <cstddef>

#define T_  512
#define B_  32
#define D_  512
#define H_  1024
#define M_  (T_ * B_)      // 16384
#define BH_ (B_ * H_)      // 32768

// Scratch (static device globals; no allocation at runtime)
__device__ float g_xT [M_ * D_];   // x transposed to [T, B, D]
__device__ float g_cur[M_ * H_];   // currents [T, B, H]
__device__ float g_spk[M_ * H_];   // spikes   [T, B, H]

// ---------------------------------------------------------------------------
// Transpose x [B, T, D] -> [T, B, D]. Fully coalesced both sides.
// ---------------------------------------------------------------------------
__global__ void transpose_kernel(const float* __restrict__ x)
{
    int idx = blockIdx.x * blockDim.x + threadIdx.x;   // over M_*D_
    if (idx >= M_ * D_) return;
    int d  = idx % D_;
    int tb = idx / D_;
    int b  = tb % B_;
    int t  = tb / B_;
    g_xT[idx] = x[((size_t)b * T_ + t) * D_ + d];
}

// ---------------------------------------------------------------------------
// fp32 GEMM: C[m, n] = sum_k A[m, k] * W[n, k] + bias[n]
// A: [M_, K] row-major, W: [H_, K] row-major, C: [M_, H_].
// 128x128 tile, BK=16, 256 threads, 8x8 per-thread microtile.
// Accumulation order: k strictly ascending with a single accumulator
// (matches the naive contraction order as closely as possible).
// ---------------------------------------------------------------------------
template<int K>
__global__ void __launch_bounds__(256, 2)
gemm_kernel(const float* __restrict__ A,
            const float* __restrict__ W,
            const float* __restrict__ bias,
            float* __restrict__ C)
{
    __shared__ float As[16][128 + 4];
    __shared__ float Bs[16][128 + 4];

    const int m0  = blockIdx.y * 128;
    const int n0  = blockIdx.x * 128;
    const int tid = threadIdx.x;
    const int tm  = tid >> 4;          // 0..15
    const int tn  = tid & 15;          // 0..15

    float acc[8][8];
    #pragma unroll
    for (int i = 0; i < 8; i++)
        #pragma unroll
        for (int j = 0; j < 8; j++)
            acc[i][j] = 0.0f;

    for (int k0 = 0; k0 < K; k0 += 16) {
        // Load 128x16 tiles of A and W, transposed into shared memory.
        #pragma unroll
        for (int i = 0; i < 2; i++) {
            int f   = tid * 2 + i;       // 0..511
            int row = f >> 2;            // 0..127
            int c   = (f & 3) * 4;       // 0,4,8,12
            float4 va = *(const float4*)(A + (size_t)(m0 + row) * K + k0 + c);
            As[c + 0][row] = va.x;
            As[c + 1][row] = va.y;
            As[c + 2][row] = va.z;
            As[c + 3][row] = va.w;
            float4 vb = *(const float4*)(W + (size_t)(n0 + row) * K + k0 + c);
            Bs[c + 0][row] = vb.x;
            Bs[c + 1][row] = vb.y;
            Bs[c + 2][row] = vb.z;
            Bs[c + 3][row] = vb.w;
        }
        __syncthreads();

        #pragma unroll
        for (int kk = 0; kk < 16; kk++) {
            float a[8], b[8];
            float4 a0 = *(const float4*)&As[kk][tm * 8];
            float4 a1 = *(const float4*)&As[kk][tm * 8 + 4];
            float4 b0 = *(const float4*)&Bs[kk][tn * 8];
            float4 b1 = *(const float4*)&Bs[kk][tn * 8 + 4];
            a[0]=a0.x; a[1]=a0.y; a[2]=a0.z; a[3]=a0.w;
            a[4]=a1.x; a[5]=a1.y; a[6]=a1.z; a[7]=a1.w;
            b[0]=b0.x; b[1]=b0.y; b[2]=b0.z; b[3]=b0.w;
            b[4]=b1.x; b[5]=b1.y; b[6]=b1.z; b[7]=b1.w;
            #pragma unroll
            for (int i = 0; i < 8; i++)
                #pragma unroll
                for (int j = 0; j < 8; j++)
                    acc[i][j] = fmaf(a[i], b[j], acc[i][j]);
        }
        __syncthreads();
    }

    // Epilogue: add bias, store.
    #pragma unroll
    for (int i = 0; i < 8; i++) {
        int m = m0 + tm * 8 + i;
        #pragma unroll
        for (int j = 0; j < 8; j++) {
            int n = n0 + tn * 8 + j;
            C[(size_t)m * H_ + n] = acc[i][j] + bias[n];
        }
    }
}

// ---------------------------------------------------------------------------
// Serial LIF scan over T.  One thread per (b, h) column.
// u_cur = 0.5*u + I;  s = (u_cur - 0.5 >= 0);  u = u_cur * (1 - s)
// OUT_BTH: write spikes to [B, T, H] (final output) instead of [T, B, H].
// ---------------------------------------------------------------------------
template<bool OUT_BTH>
__global__ void scan_kernel(const float* __restrict__ I, float* __restrict__ S)
{
    int idx = blockIdx.x * blockDim.x + threadIdx.x;   // 0..BH_-1
    if (idx >= BH_) return;

    const float* ip = I + idx;
    float* sp;
    if (OUT_BTH) {
        int b = idx / H_;
        int h = idx % H_;
        sp = S + (size_t)b * T_ * H_ + h;
    } else {
        sp = S + idx;
    }

    float u = 0.0f;
    #pragma unroll 16
    for (int t = 0; t < T_; t++) {
        float cur = ip[(size_t)t * BH_];
        u = 0.5f * u + cur;
        float v = u - 0.5f;
        float s = (v >= 0.0f) ? 1.0f : 0.0f;
        if (OUT_BTH) sp[(size_t)t * H_] = s;
        else         sp[(size_t)t * BH_] = s;
        u = (v >= 0.0f) ? 0.0f : u;
    }
}

// ---------------------------------------------------------------------------
// Launch
// ---------------------------------------------------------------------------
extern "C" void kernel_launch(void* const* d_in, const int* in_sizes, int n_in,
                              void* d_out, int out_size)
{
    const float* x  = (const float*)d_in[0];
    const float* W0 = (const float*)d_in[1];
    const float* b0 = (const float*)d_in[2];
    const float* W1 = (const float*)d_in[3];
    const float* b1 = (const float*)d_in[4];
    const float* W2 = (const float*)d_in[5];
    const float* b2 = (const float*)d_in[6];
    float* out = (float*)d_out;

    float *xT, *cur, *spk;
    cudaGetSymbolAddress((void**)&xT,  g_xT);
    cudaGetSymbolAddress((void**)&cur, g_cur);
    cudaGetSymbolAddress((void**)&spk, g_spk);

    // 1) transpose x -> [T, B, D]
    {
        int n = M_ * D_;
        transpose_kernel<<<(n + 255) / 256, 256>>>(x);
    }

    dim3 ggrid(H_ / 128, M_ / 128);   // (8, 128)

    // Layer 0
    gemm_kernel<D_><<<ggrid, 256>>>(xT, W0, b0, cur);
    scan_kernel<false><<<BH_ / 256, 256>>>(cur, spk);

    // Layer 1
    gemm_kernel<H_><<<ggrid, 256>>>(spk, W1, b1, cur);
    scan_kernel<false><<<BH_ / 256, 256>>>(cur, spk);

    // Layer 2
    gemm_kernel<H_><<<ggrid, 256>>>(spk, W2, b2, cur);
    scan_kernel<true><<<BH_ / 256, 256>>>(cur, out);
}

// round 5
// speedup vs baseline: 1.7751x; 1.7751x over previous
#include <cuda_runtime.h>
#include <cuda_bf16.h>
#include <cstdint>
#include <cstddef>

#define T_  512
#define B_  32
#define D_  512
#define H_  1024
#define M_  (T_ * B_)      // 16384
#define BH_ (B_ * H_)      // 32768
#define KEFF 3072
#define NCHUNK 48          // KEFF / 64
#define NSTAGE 3
#define A_BYTES  16384     // 128 x 64 bf16
#define B_BYTES  32768     // 256 x 64 bf16
#define STAGE_BYTES (A_BYTES + B_BYTES)        // 49152
#define BIAS_OFF (NSTAGE * STAGE_BYTES)        // 147456
#define SMEM_TOTAL (BIAS_OFF + 1024 + 128)

// ---------------- scratch (static device globals) ----------------
__device__ __nv_bfloat16 g_x0[M_ * D_];
__device__ __nv_bfloat16 g_x1[M_ * D_];
__device__ __nv_bfloat16 g_x2[M_ * D_];
__device__ __nv_bfloat16 g_spk[M_ * H_];          // spikes bf16 [T,B,H]
__device__ float         g_cur[M_ * H_];          // currents fp32 [T,B,H]
__device__ __nv_bfloat16 g_wext[3][H_ * KEFF];    // extended-K weight planes

// ---------------- PTX helpers (sm_100-baseline only) ----------------
__device__ __forceinline__ uint32_t smem_u32(const void* p) {
    uint32_t a;
    asm("{ .reg .u64 t; cvta.to.shared.u64 t, %1; cvt.u32.u64 %0, t; }" : "=r"(a) : "l"(p));
    return a;
}
__device__ __forceinline__ void cp_async16(uint32_t saddr, const void* gaddr) {
    asm volatile("cp.async.cg.shared.global [%0], [%1], 16;" :: "r"(saddr), "l"(gaddr) : "memory");
}
__device__ __forceinline__ void cp_commit() {
    asm volatile("cp.async.commit_group;" ::: "memory");
}
__device__ __forceinline__ void cp_wait1() {
    asm volatile("cp.async.wait_group 1;" ::: "memory");
}
__device__ __forceinline__ void cp_wait0() {
    asm volatile("cp.async.wait_group 0;" ::: "memory");
}
__device__ __forceinline__ void ldsm_x4(uint32_t* r, uint32_t addr) {
    asm volatile("ldmatrix.sync.aligned.m8n8.x4.shared.b16 {%0,%1,%2,%3}, [%4];"
                 : "=r"(r[0]), "=r"(r[1]), "=r"(r[2]), "=r"(r[3]) : "r"(addr));
}
__device__ __forceinline__ void mma16816(float* d, const uint32_t* a, uint32_t b0, uint32_t b1) {
    asm volatile(
        "mma.sync.aligned.m16n8k16.row.col.f32.bf16.bf16.f32 "
        "{%0,%1,%2,%3}, {%4,%5,%6,%7}, {%8,%9}, {%0,%1,%2,%3};"
        : "+f"(d[0]), "+f"(d[1]), "+f"(d[2]), "+f"(d[3])
        : "r"(a[0]), "r"(a[1]), "r"(a[2]), "r"(a[3]), "r"(b0), "r"(b1));
}

// ---------------- prep: transpose x + 3-way bf16 split ----------------
__global__ void prep_x_kernel(const float* __restrict__ x)
{
    int idx = blockIdx.x * blockDim.x + threadIdx.x;
    if (idx >= M_ * D_) return;
    int d  = idx % D_;
    int tb = idx / D_;
    int b  = tb % B_;
    int t  = tb / B_;
    float v = x[((size_t)b * T_ + t) * D_ + d];
    __nv_bfloat16 p0 = __float2bfloat16(v);
    float r = v - __bfloat162float(p0);
    __nv_bfloat16 p1 = __float2bfloat16(r);
    r -= __bfloat162float(p1);
    __nv_bfloat16 p2 = __float2bfloat16(r);
    g_x0[idx] = p0; g_x1[idx] = p1; g_x2[idx] = p2;
}

// ---------------- weight split into extended-K planes ----------------
__global__ void split_w_kernel(const float* __restrict__ W, __nv_bfloat16* __restrict__ dst,
                               int K, int G, int s0, int s1, int s2, int s3, int s4, int s5)
{
    int idx = blockIdx.x * blockDim.x + threadIdx.x;
    if (idx >= H_ * K) return;
    int n = idx / K, k = idx % K;
    float w = W[(size_t)n * K + k];
    __nv_bfloat16 p[3];
    p[0] = __float2bfloat16(w);
    float r = w - __bfloat162float(p[0]);
    p[1] = __float2bfloat16(r);
    r -= __bfloat162float(p[1]);
    p[2] = __float2bfloat16(r);
    int seq[6] = {s0, s1, s2, s3, s4, s5};
    for (int g = 0; g < G; g++)
        dst[(size_t)n * KEFF + (size_t)g * K + k] = p[seq[g]];
}

// ---------------- warp-MMA GEMM: C = sum_planes A_p @ Wext^T + bias ----------------
// Key numerics property: tensor-core fp32 accumulation (RZ/truncating) is limited
// to 2 chained mma per output tile; chunk partials are folded into the persistent
// accumulator with fp32 RN adds. Keeps total error ~1e-6 (fp32-GEMM class).
struct GemmArgs {
    const __nv_bfloat16* a[6];   // A plane base per K-group, [M_, KPLANE] bf16
    const __nv_bfloat16* w;      // [H_, KEFF] bf16
    const float* bias;           // [H_]
    float* c;                    // [M_, H_] fp32
};

template<int KPLANE, int CPG_LOG2>
__global__ void __launch_bounds__(256, 1)
gemm_mma(GemmArgs args)
{
    extern __shared__ char smem[];
    const uint32_t sb = smem_u32(smem);
    const int tid  = threadIdx.x;
    const int wid  = tid >> 5;
    const int lane = tid & 31;

    const int tile_n = blockIdx.x & 3;         // N/256 = 4
    const int tile_m = blockIdx.x >> 2;        // M/128 = 128
    const int m0 = tile_m * 128;
    const int n0 = tile_n * 256;

    float* bias_s = (float*)(smem + BIAS_OFF);
    bias_s[tid] = args.bias[n0 + tid];

    const int lrow = tid >> 3;                 // 0..31
    const int lc   = tid & 7;                  // 0..7

    // per-thread cp.async loader for one BK=64 chunk into stage s
    auto load_stage = [&](int ch, int s) {
        const int grp = ch >> CPG_LOG2;
        const int kin = (ch & ((1 << CPG_LOG2) - 1)) * 64;
        const __nv_bfloat16* Ap = args.a[grp];
        const uint32_t sa = sb + s * STAGE_BYTES;
        const uint32_t sB = sa + A_BYTES;
        #pragma unroll
        for (int p = 0; p < 4; p++) {          // A: 128 rows
            const int row = lrow + 32 * p;
            const uint32_t dst = sa + (uint32_t)(row * 128 + ((lc ^ (row & 7)) * 16));
            cp_async16(dst, Ap + (size_t)(m0 + row) * KPLANE + kin + lc * 8);
        }
        #pragma unroll
        for (int p = 0; p < 8; p++) {          // B: 256 rows
            const int row = lrow + 32 * p;
            const uint32_t dst = sB + (uint32_t)(row * 128 + ((lc ^ (row & 7)) * 16));
            cp_async16(dst, args.w + (size_t)(n0 + row) * KEFF + (size_t)ch * 64 + lc * 8);
        }
        cp_commit();
    };

    float acc[4][8][4];
    #pragma unroll
    for (int i = 0; i < 4; i++)
        #pragma unroll
        for (int j = 0; j < 8; j++)
            #pragma unroll
            for (int e = 0; e < 4; e++) acc[i][j][e] = 0.0f;

    const int wm = (wid & 1) * 64;             // warp row offset in CTA
    const int wn = (wid >> 1) * 64;            // warp col offset in CTA

    // prologue: stages 0..NSTAGE-2
    #pragma unroll
    for (int s = 0; s < NSTAGE - 1; s++) load_stage(s, s);

    for (int ch = 0; ch < NCHUNK; ch++) {
        // On the final chunk only one group is pending -> wait_group 0.
        if (ch < NCHUNK - 1) cp_wait1(); else cp_wait0();
        __syncthreads();
        const int nc = ch + NSTAGE - 1;
        if (nc < NCHUNK) load_stage(nc, nc % NSTAGE);

        const uint32_t sa = sb + (ch % NSTAGE) * STAGE_BYTES;
        const uint32_t sB = sa + A_BYTES;

        // Process chunk as two k32 halves; each output tile gets a fresh
        // zeroed tensor-core accumulator per half, folded back with RN FADD.
        #pragma unroll
        for (int half = 0; half < 2; half++) {
            uint32_t ar[2][4][4], br[2][4][4];
            #pragma unroll
            for (int k = 0; k < 2; k++) {
                const int k16 = half * 2 + k;
                #pragma unroll
                for (int mt = 0; mt < 4; mt++) {
                    const int row = wm + mt * 16 + (lane & 15);
                    const int c   = 2 * k16 + (lane >> 4);
                    ldsm_x4(ar[k][mt], sa + (uint32_t)(row * 128 + ((c ^ (row & 7)) * 16)));
                }
                #pragma unroll
                for (int nt = 0; nt < 4; nt++) {
                    const int row = wn + nt * 16 + (lane & 7) + (lane >> 4) * 8;
                    const int c   = 2 * k16 + ((lane >> 3) & 1);
                    ldsm_x4(br[k][nt], sB + (uint32_t)(row * 128 + ((c ^ (row & 7)) * 16)));
                }
            }
            #pragma unroll
            for (int mt = 0; mt < 4; mt++)
                #pragma unroll
                for (int nt = 0; nt < 4; nt++) {
                    float t0[4] = {0.f, 0.f, 0.f, 0.f};
                    mma16816(t0, ar[0][mt], br[0][nt][0], br[0][nt][1]);
                    mma16816(t0, ar[1][mt], br[1][nt][0], br[1][nt][1]);
                    float t1[4] = {0.f, 0.f, 0.f, 0.f};
                    mma16816(t1, ar[0][mt], br[0][nt][2], br[0][nt][3]);
                    mma16816(t1, ar[1][mt], br[1][nt][2], br[1][nt][3]);
                    #pragma unroll
                    for (int e = 0; e < 4; e++) {
                        acc[mt][2 * nt][e]     += t0[e];
                        acc[mt][2 * nt + 1][e] += t1[e];
                    }
                }
        }
    }
    __syncthreads();   // all cp.async drained by wait0 on final chunk

    // ---- epilogue: regs -> smem staging -> coalesced fp32 stores (+bias) ----
    float* stg = (float*)smem;                 // 128 x 260 floats (133 KB)
    #pragma unroll
    for (int mt = 0; mt < 4; mt++) {
        #pragma unroll
        for (int j = 0; j < 8; j++) {
            const int r0 = wm + mt * 16 + lane / 4;
            const int cc = wn + j * 8 + 2 * (lane % 4);
            stg[r0 * 260 + cc]           = acc[mt][j][0];
            stg[r0 * 260 + cc + 1]       = acc[mt][j][1];
            stg[(r0 + 8) * 260 + cc]     = acc[mt][j][2];
            stg[(r0 + 8) * 260 + cc + 1] = acc[mt][j][3];
        }
    }
    __syncthreads();
    #pragma unroll 4
    for (int it = 0; it < 32; it++) {
        const int idx = it * 1024 + tid * 4;
        const int row = idx >> 8, col = idx & 255;
        float4 v = *(const float4*)&stg[row * 260 + col];
        v.x += bias_s[col];
        v.y += bias_s[col + 1];
        v.z += bias_s[col + 2];
        v.w += bias_s[col + 3];
        *(float4*)&args.c[(size_t)(m0 + row) * H_ + n0 + col] = v;
    }
}

// ---------------- serial LIF scan ----------------
template<bool FINAL_OUT>
__global__ void scan_kernel(const float* __restrict__ I,
                            __nv_bfloat16* __restrict__ Sb,
                            float* __restrict__ Of)
{
    int idx = blockIdx.x * blockDim.x + threadIdx.x;
    if (idx >= BH_) return;
    const int b = idx / H_;
    const int h = idx % H_;
    float u = 0.0f;
    #pragma unroll 16
    for (int t = 0; t < T_; t++) {
        float cur = I[(size_t)t * BH_ + idx];
        u = 0.5f * u + cur;
        float v = u - 0.5f;
        bool fire = (v >= 0.0f);
        if (FINAL_OUT) Of[((size_t)b * T_ + t) * H_ + h] = fire ? 1.0f : 0.0f;
        else           Sb[(size_t)t * BH_ + idx] = __float2bfloat16(fire ? 1.0f : 0.0f);
        u = fire ? 0.0f : u;
    }
}

// ---------------- launch ----------------
extern "C" void kernel_launch(void* const* d_in, const int* in_sizes, int n_in,
                              void* d_out, int out_size)
{
    const float* x  = (const float*)d_in[0];
    const float* W0 = (const float*)d_in[1];
    const float* b0 = (const float*)d_in[2];
    const float* W1 = (const float*)d_in[3];
    const float* b1 = (const float*)d_in[4];
    const float* W2 = (const float*)d_in[5];
    const float* b2 = (const float*)d_in[6];
    float* out = (float*)d_out;

    __nv_bfloat16 *x0, *x1, *x2, *spk, *wext;
    float* cur;
    cudaGetSymbolAddress((void**)&x0,  g_x0);
    cudaGetSymbolAddress((void**)&x1,  g_x1);
    cudaGetSymbolAddress((void**)&x2,  g_x2);
    cudaGetSymbolAddress((void**)&spk, g_spk);
    cudaGetSymbolAddress((void**)&cur, g_cur);
    cudaGetSymbolAddress((void**)&wext, g_wext);
    __nv_bfloat16* we0 = wext;
    __nv_bfloat16* we1 = wext + (size_t)H_ * KEFF;
    __nv_bfloat16* we2 = wext + (size_t)2 * H_ * KEFF;

    cudaFuncSetAttribute(gemm_mma<512, 3>,  cudaFuncAttributeMaxDynamicSharedMemorySize, SMEM_TOTAL);
    cudaFuncSetAttribute(gemm_mma<1024, 4>, cudaFuncAttributeMaxDynamicSharedMemorySize, SMEM_TOTAL);

    // prep
    prep_x_kernel<<<(M_ * D_ + 255) / 256, 256>>>(x);
    // layer0 pair sequence: A:{x0,x0,x1,x0,x1,x2}  W:{w0,w1,w0,w2,w1,w0}
    split_w_kernel<<<(H_ * D_ + 255) / 256, 256>>>(W0, we0, D_, 6, 0, 1, 0, 2, 1, 0);
    split_w_kernel<<<(H_ * H_ + 255) / 256, 256>>>(W1, we1, H_, 3, 0, 1, 2, 0, 0, 0);
    split_w_kernel<<<(H_ * H_ + 255) / 256, 256>>>(W2, we2, H_, 3, 0, 1, 2, 0, 0, 0);

    const int GGRID = (M_ / 128) * (H_ / 256);   // 512 CTAs

    // Layer 0
    {
        GemmArgs a;
        a.a[0] = x0; a.a[1] = x0; a.a[2] = x1; a.a[3] = x0; a.a[4] = x1; a.a[5] = x2;
        a.w = we0; a.bias = b0; a.c = cur;
        gemm_mma<512, 3><<<GGRID, 256, SMEM_TOTAL>>>(a);
    }
    scan_kernel<false><<<BH_ / 256, 256>>>(cur, spk, nullptr);

    // Layer 1
    {
        GemmArgs a;
        for (int i = 0; i < 6; i++) a.a[i] = spk;
        a.w = we1; a.bias = b1; a.c = cur;
        gemm_mma<1024, 4><<<GGRID, 256, SMEM_TOTAL>>>(a);
    }
    scan_kernel<false><<<BH_ / 256, 256>>>(cur, spk, nullptr);

    // Layer 2
    {
        GemmArgs a;
        for (int i = 0; i < 6; i++) a.a[i] = spk;
        a.w = we2; a.bias = b2; a.c = cur;
        gemm_mma<1024, 4><<<GGRID, 256, SMEM_TOTAL>>>(a);
    }
    scan_kernel<true><<<BH_ / 256, 256>>>(cur, nullptr, out);
}

// round 6
// speedup vs baseline: 2.3757x; 1.3383x over previous
#include <cuda_runtime.h>
#include <cuda_bf16.h>
#include <cstdint>
#include <cstddef>

#define T_  512
#define B_  32
#define D_  512
#define H_  1024
#define M_  (T_ * B_)      // 16384
#define BH_ (B_ * H_)      // 32768

// ---- bf16 path (layer 0) ----
#define KEFF 3072
#define NCHUNK 48          // KEFF / 64
#define NSTAGE 3
#define A_BYTES  16384     // 128 x 64 bf16
#define B_BYTES  32768     // 256 x 64 bf16
#define STAGE_BYTES (A_BYTES + B_BYTES)        // 49152
#define BIAS_OFF (NSTAGE * STAGE_BYTES)        // 147456
#define SMEM_TOTAL (BIAS_OFF + 1024 + 128)

// ---- int8 path (layers 1, 2) ----
#define KI8      4096      // 4 planes x 1024
#define NCH_I8   32        // KI8 / 128
#define I8_STAGE 32768     // A 128x128B + B 128x128B
#define I8_BIAS_OFF (3 * I8_STAGE)             // 98304
#define I8_SMEM (I8_BIAS_OFF + 512 + 128)

// ---------------- scratch (static device globals) ----------------
__device__ __nv_bfloat16 g_x0[M_ * D_];
__device__ __nv_bfloat16 g_x1[M_ * D_];
__device__ __nv_bfloat16 g_x2[M_ * D_];
__device__ __align__(256) char g_spk[M_ * H_];    // spikes s8 [T,B,H]
__device__ float         g_cur[M_ * H_];          // currents fp32 [T,B,H]
__device__ __nv_bfloat16 g_wext[H_ * KEFF];       // layer0 extended-K bf16 planes
__device__ __align__(256) char g_wq[2][H_ * KI8]; // layers1,2 int8 weight planes

// ---------------- PTX helpers (sm_100-baseline only) ----------------
__device__ __forceinline__ uint32_t smem_u32(const void* p) {
    uint32_t a;
    asm("{ .reg .u64 t; cvta.to.shared.u64 t, %1; cvt.u32.u64 %0, t; }" : "=r"(a) : "l"(p));
    return a;
}
__device__ __forceinline__ void cp_async16(uint32_t saddr, const void* gaddr) {
    asm volatile("cp.async.cg.shared.global [%0], [%1], 16;" :: "r"(saddr), "l"(gaddr) : "memory");
}
__device__ __forceinline__ void cp_commit() {
    asm volatile("cp.async.commit_group;" ::: "memory");
}
__device__ __forceinline__ void cp_wait1() {
    asm volatile("cp.async.wait_group 1;" ::: "memory");
}
__device__ __forceinline__ void cp_wait0() {
    asm volatile("cp.async.wait_group 0;" ::: "memory");
}
__device__ __forceinline__ void ldsm_x4(uint32_t* r, uint32_t addr) {
    asm volatile("ldmatrix.sync.aligned.m8n8.x4.shared.b16 {%0,%1,%2,%3}, [%4];"
                 : "=r"(r[0]), "=r"(r[1]), "=r"(r[2]), "=r"(r[3]) : "r"(addr));
}
__device__ __forceinline__ void mma16816(float* d, const uint32_t* a, uint32_t b0, uint32_t b1) {
    asm volatile(
        "mma.sync.aligned.m16n8k16.row.col.f32.bf16.bf16.f32 "
        "{%0,%1,%2,%3}, {%4,%5,%6,%7}, {%8,%9}, {%0,%1,%2,%3};"
        : "+f"(d[0]), "+f"(d[1]), "+f"(d[2]), "+f"(d[3])
        : "r"(a[0]), "r"(a[1]), "r"(a[2]), "r"(a[3]), "r"(b0), "r"(b1));
}
__device__ __forceinline__ void imma16832(int* d, const uint32_t* a, uint32_t b0, uint32_t b1) {
    asm volatile(
        "mma.sync.aligned.m16n8k32.row.col.s32.s8.s8.s32 "
        "{%0,%1,%2,%3}, {%4,%5,%6,%7}, {%8,%9}, {%0,%1,%2,%3};"
        : "+r"(d[0]), "+r"(d[1]), "+r"(d[2]), "+r"(d[3])
        : "r"(a[0]), "r"(a[1]), "r"(a[2]), "r"(a[3]), "r"(b0), "r"(b1));
}

// ---------------- prep: transpose x + 3-way bf16 split ----------------
__global__ void prep_x_kernel(const float* __restrict__ x)
{
    int idx = blockIdx.x * blockDim.x + threadIdx.x;
    if (idx >= M_ * D_) return;
    int d  = idx % D_;
    int tb = idx / D_;
    int b  = tb % B_;
    int t  = tb / B_;
    float v = x[((size_t)b * T_ + t) * D_ + d];
    __nv_bfloat16 p0 = __float2bfloat16(v);
    float r = v - __bfloat162float(p0);
    __nv_bfloat16 p1 = __float2bfloat16(r);
    r -= __bfloat162float(p1);
    __nv_bfloat16 p2 = __float2bfloat16(r);
    g_x0[idx] = p0; g_x1[idx] = p1; g_x2[idx] = p2;
}

// ---------------- layer-0 weight split into extended-K bf16 planes ----------------
__global__ void split_w_kernel(const float* __restrict__ W, __nv_bfloat16* __restrict__ dst,
                               int K, int s0, int s1, int s2, int s3, int s4, int s5)
{
    int idx = blockIdx.x * blockDim.x + threadIdx.x;
    if (idx >= H_ * K) return;
    int n = idx / K, k = idx % K;
    float w = W[(size_t)n * K + k];
    __nv_bfloat16 p[3];
    p[0] = __float2bfloat16(w);
    float r = w - __bfloat162float(p[0]);
    p[1] = __float2bfloat16(r);
    r -= __bfloat162float(p[1]);
    p[2] = __float2bfloat16(r);
    int seq[6] = {s0, s1, s2, s3, s4, s5};
    for (int g = 0; g < 6; g++)
        dst[(size_t)n * KEFF + (size_t)g * K + k] = p[seq[g]];
}

// ---------------- layers-1,2 weight quantization: 4 radix-2^7 s8 planes, S=2^12 ----
// w_hat = (q0 + q1*2^-7 + q2*2^-14 + q3*2^-21) / 2^12; all arithmetic exact in fp32.
__global__ void quant_w_kernel(const float* __restrict__ W, char* __restrict__ dst)
{
    int idx = blockIdx.x * blockDim.x + threadIdx.x;
    if (idx >= H_ * H_) return;
    int n = idx / H_, k = idx % H_;
    float r = W[idx] * 4096.0f;                 // exact (power of 2)
    #pragma unroll
    for (int g = 0; g < 4; g++) {
        float q = fminf(fmaxf(rintf(r), -127.0f), 127.0f);
        dst[(size_t)n * KI8 + (size_t)g * H_ + k] = (char)(int)q;
        r = (r - q) * 128.0f;                   // exact
    }
}

// ---------------- bf16 warp-MMA GEMM (layer 0): C = sum_planes A_p @ Wext^T + bias ----
// tensor-core fp32 accumulation (RZ) limited to 2 chained mma; folded with RN FADD.
struct GemmArgs {
    const __nv_bfloat16* a[6];
    const __nv_bfloat16* w;
    const float* bias;
    float* c;
};

template<int KPLANE, int CPG_LOG2>
__global__ void __launch_bounds__(256, 1)
gemm_mma(GemmArgs args)
{
    extern __shared__ char smem[];
    const uint32_t sb = smem_u32(smem);
    const int tid  = threadIdx.x;
    const int wid  = tid >> 5;
    const int lane = tid & 31;

    const int tile_n = blockIdx.x & 3;
    const int tile_m = blockIdx.x >> 2;
    const int m0 = tile_m * 128;
    const int n0 = tile_n * 256;

    float* bias_s = (float*)(smem + BIAS_OFF);
    bias_s[tid] = args.bias[n0 + tid];

    const int lrow = tid >> 3;
    const int lc   = tid & 7;

    auto load_stage = [&](int ch, int s) {
        const int grp = ch >> CPG_LOG2;
        const int kin = (ch & ((1 << CPG_LOG2) - 1)) * 64;
        const __nv_bfloat16* Ap = args.a[grp];
        const uint32_t sa = sb + s * STAGE_BYTES;
        const uint32_t sB = sa + A_BYTES;
        #pragma unroll
        for (int p = 0; p < 4; p++) {
            const int row = lrow + 32 * p;
            const uint32_t dst = sa + (uint32_t)(row * 128 + ((lc ^ (row & 7)) * 16));
            cp_async16(dst, Ap + (size_t)(m0 + row) * KPLANE + kin + lc * 8);
        }
        #pragma unroll
        for (int p = 0; p < 8; p++) {
            const int row = lrow + 32 * p;
            const uint32_t dst = sB + (uint32_t)(row * 128 + ((lc ^ (row & 7)) * 16));
            cp_async16(dst, args.w + (size_t)(n0 + row) * KEFF + (size_t)ch * 64 + lc * 8);
        }
        cp_commit();
    };

    float acc[4][8][4];
    #pragma unroll
    for (int i = 0; i < 4; i++)
        #pragma unroll
        for (int j = 0; j < 8; j++)
            #pragma unroll
            for (int e = 0; e < 4; e++) acc[i][j][e] = 0.0f;

    const int wm = (wid & 1) * 64;
    const int wn = (wid >> 1) * 64;

    #pragma unroll
    for (int s = 0; s < NSTAGE - 1; s++) load_stage(s, s);

    for (int ch = 0; ch < NCHUNK; ch++) {
        if (ch < NCHUNK - 1) cp_wait1(); else cp_wait0();
        __syncthreads();
        const int nc = ch + NSTAGE - 1;
        if (nc < NCHUNK) load_stage(nc, nc % NSTAGE);

        const uint32_t sa = sb + (ch % NSTAGE) * STAGE_BYTES;
        const uint32_t sB = sa + A_BYTES;

        #pragma unroll
        for (int half = 0; half < 2; half++) {
            uint32_t ar[2][4][4], br[2][4][4];
            #pragma unroll
            for (int k = 0; k < 2; k++) {
                const int k16 = half * 2 + k;
                #pragma unroll
                for (int mt = 0; mt < 4; mt++) {
                    const int row = wm + mt * 16 + (lane & 15);
                    const int c   = 2 * k16 + (lane >> 4);
                    ldsm_x4(ar[k][mt], sa + (uint32_t)(row * 128 + ((c ^ (row & 7)) * 16)));
                }
                #pragma unroll
                for (int nt = 0; nt < 4; nt++) {
                    const int row = wn + nt * 16 + (lane & 7) + (lane >> 4) * 8;
                    const int c   = 2 * k16 + ((lane >> 3) & 1);
                    ldsm_x4(br[k][nt], sB + (uint32_t)(row * 128 + ((c ^ (row & 7)) * 16)));
                }
            }
            #pragma unroll
            for (int mt = 0; mt < 4; mt++)
                #pragma unroll
                for (int nt = 0; nt < 4; nt++) {
                    float t0[4] = {0.f, 0.f, 0.f, 0.f};
                    mma16816(t0, ar[0][mt], br[0][nt][0], br[0][nt][1]);
                    mma16816(t0, ar[1][mt], br[1][nt][0], br[1][nt][1]);
                    float t1[4] = {0.f, 0.f, 0.f, 0.f};
                    mma16816(t1, ar[0][mt], br[0][nt][2], br[0][nt][3]);
                    mma16816(t1, ar[1][mt], br[1][nt][2], br[1][nt][3]);
                    #pragma unroll
                    for (int e = 0; e < 4; e++) {
                        acc[mt][2 * nt][e]     += t0[e];
                        acc[mt][2 * nt + 1][e] += t1[e];
                    }
                }
        }
    }
    __syncthreads();

    float* stg = (float*)smem;
    #pragma unroll
    for (int mt = 0; mt < 4; mt++) {
        #pragma unroll
        for (int j = 0; j < 8; j++) {
            const int r0 = wm + mt * 16 + lane / 4;
            const int cc = wn + j * 8 + 2 * (lane % 4);
            stg[r0 * 260 + cc]           = acc[mt][j][0];
            stg[r0 * 260 + cc + 1]       = acc[mt][j][1];
            stg[(r0 + 8) * 260 + cc]     = acc[mt][j][2];
            stg[(r0 + 8) * 260 + cc + 1] = acc[mt][j][3];
        }
    }
    __syncthreads();
    #pragma unroll 4
    for (int it = 0; it < 32; it++) {
        const int idx = it * 1024 + tid * 4;
        const int row = idx >> 8, col = idx & 255;
        float4 v = *(const float4*)&stg[row * 260 + col];
        v.x += bias_s[col];
        v.y += bias_s[col + 1];
        v.z += bias_s[col + 2];
        v.w += bias_s[col + 3];
        *(float4*)&args.c[(size_t)(m0 + row) * H_ + n0 + col] = v;
    }
}

// ---------------- int8 warp-IMMA GEMM (layers 1,2) ----------------
// C = (sum_g 2^(-7g) * (S_g @ Wq_g^T)) / 2^12 + bias, s32 accumulation EXACT.
// CTA 128x128, 8 warps (2m x 4n), warp tile 64x32, BK=128 int8, 3-stage cp.async.
__global__ void __launch_bounds__(256, 1)
gemm_i8(const char* __restrict__ A, const char* __restrict__ W8,
        const float* __restrict__ bias, float* __restrict__ C)
{
    extern __shared__ char smem[];
    const uint32_t sb = smem_u32(smem);
    const int tid  = threadIdx.x;
    const int wid  = tid >> 5;
    const int lane = tid & 31;

    const int tile_n = blockIdx.x & 7;         // H/128 = 8
    const int tile_m = blockIdx.x >> 3;        // M/128 = 128
    const int m0 = tile_m * 128;
    const int n0 = tile_n * 128;

    float* bias_s = (float*)(smem + I8_BIAS_OFF);
    if (tid < 128) bias_s[tid] = bias[n0 + tid];

    const int lrow = tid >> 3;                 // 0..31
    const int lc   = tid & 7;                  // 0..7

    auto load_stage = [&](int ch, int s) {
        const int kin = (ch & 7) * 128;        // spike A offset within H row
        const uint32_t sa = sb + s * I8_STAGE;
        const uint32_t sB = sa + 16384;
        #pragma unroll
        for (int p = 0; p < 4; p++) {          // A: 128 rows x 128B
            const int row = lrow + 32 * p;
            const uint32_t dst = sa + (uint32_t)(row * 128 + ((lc ^ (row & 7)) * 16));
            cp_async16(dst, A + (size_t)(m0 + row) * H_ + kin + lc * 16);
        }
        #pragma unroll
        for (int p = 0; p < 4; p++) {          // B: 128 rows x 128B
            const int row = lrow + 32 * p;
            const uint32_t dst = sB + (uint32_t)(row * 128 + ((lc ^ (row & 7)) * 16));
            cp_async16(dst, W8 + (size_t)(n0 + row) * KI8 + (size_t)ch * 128 + lc * 16);
        }
        cp_commit();
    };

    float facc[4][4][4];
    int   iacc[4][4][4];
    #pragma unroll
    for (int i = 0; i < 4; i++)
        #pragma unroll
        for (int j = 0; j < 4; j++)
            #pragma unroll
            for (int e = 0; e < 4; e++) { facc[i][j][e] = 0.0f; iacc[i][j][e] = 0; }

    const int wm = (wid & 1) * 64;             // 2 warps over M
    const int wn = (wid >> 1) * 32;            // 4 warps over N

    // group fold scales: 2^(-7g-12), exact powers of two
    const float fscale[4] = {2.44140625e-4f, 1.9073486328125e-6f,
                             1.4901161193847656e-8f, 1.1641532182693481e-10f};

    #pragma unroll
    for (int s = 0; s < 2; s++) load_stage(s, s);

    for (int ch = 0; ch < NCH_I8; ch++) {
        if (ch < NCH_I8 - 1) cp_wait1(); else cp_wait0();
        __syncthreads();
        const int nc = ch + 2;
        if (nc < NCH_I8) load_stage(nc, nc % 3);

        const uint32_t sa = sb + (ch % 3) * I8_STAGE;
        const uint32_t sB = sa + 16384;

        #pragma unroll
        for (int k32 = 0; k32 < 4; k32++) {
            uint32_t ar[4][4];
            #pragma unroll
            for (int mt = 0; mt < 4; mt++) {
                const int row = wm + mt * 16 + (lane & 15);
                const int c   = 2 * k32 + (lane >> 4);
                ldsm_x4(ar[mt], sa + (uint32_t)(row * 128 + ((c ^ (row & 7)) * 16)));
            }
            uint32_t br[2][4];
            #pragma unroll
            for (int nt = 0; nt < 2; nt++) {
                const int row = wn + nt * 16 + (lane & 7) + (lane >> 4) * 8;
                const int c   = 2 * k32 + ((lane >> 3) & 1);
                ldsm_x4(br[nt], sB + (uint32_t)(row * 128 + ((c ^ (row & 7)) * 16)));
            }
            #pragma unroll
            for (int mt = 0; mt < 4; mt++)
                #pragma unroll
                for (int nt = 0; nt < 2; nt++) {
                    imma16832(iacc[mt][2 * nt],     ar[mt], br[nt][0], br[nt][1]);
                    imma16832(iacc[mt][2 * nt + 1], ar[mt], br[nt][2], br[nt][3]);
                }
        }

        if ((ch & 7) == 7) {                   // group boundary: exact-scale fold
            const float fs = fscale[ch >> 3];
            #pragma unroll
            for (int mt = 0; mt < 4; mt++)
                #pragma unroll
                for (int j = 0; j < 4; j++)
                    #pragma unroll
                    for (int e = 0; e < 4; e++) {
                        facc[mt][j][e] += (float)iacc[mt][j][e] * fs;
                        iacc[mt][j][e] = 0;
                    }
        }
    }
    __syncthreads();

    // epilogue: facc -> smem -> coalesced stores (+bias)
    float* stg = (float*)smem;                 // 128 x 132 floats
    #pragma unroll
    for (int mt = 0; mt < 4; mt++) {
        #pragma unroll
        for (int j = 0; j < 4; j++) {
            const int r0 = wm + mt * 16 + lane / 4;
            const int cc = wn + j * 8 + 2 * (lane % 4);
            stg[r0 * 132 + cc]           = facc[mt][j][0];
            stg[r0 * 132 + cc + 1]       = facc[mt][j][1];
            stg[(r0 + 8) * 132 + cc]     = facc[mt][j][2];
            stg[(r0 + 8) * 132 + cc + 1] = facc[mt][j][3];
        }
    }
    __syncthreads();
    #pragma unroll 4
    for (int it = 0; it < 16; it++) {
        const int idx = it * 1024 + tid * 4;
        const int row = idx >> 7, col = idx & 127;
        float4 v = *(const float4*)&stg[row * 132 + col];
        v.x += bias_s[col];
        v.y += bias_s[col + 1];
        v.z += bias_s[col + 2];
        v.w += bias_s[col + 3];
        *(float4*)&C[(size_t)(m0 + row) * H_ + n0 + col] = v;
    }
}

// ---------------- serial LIF scan ----------------
template<bool FINAL_OUT>
__global__ void scan_kernel(const float* __restrict__ I,
                            char* __restrict__ Sb,
                            float* __restrict__ Of)
{
    int idx = blockIdx.x * blockDim.x + threadIdx.x;
    if (idx >= BH_) return;
    const int b = idx / H_;
    const int h = idx % H_;
    float u = 0.0f;
    #pragma unroll 16
    for (int t = 0; t < T_; t++) {
        float cur = I[(size_t)t * BH_ + idx];
        u = 0.5f * u + cur;
        float v = u - 0.5f;
        bool fire = (v >= 0.0f);
        if (FINAL_OUT) Of[((size_t)b * T_ + t) * H_ + h] = fire ? 1.0f : 0.0f;
        else           Sb[(size_t)t * BH_ + idx] = fire ? 1 : 0;
        u = fire ? 0.0f : u;
    }
}

// ---------------- launch ----------------
extern "C" void kernel_launch(void* const* d_in, const int* in_sizes, int n_in,
                              void* d_out, int out_size)
{
    const float* x  = (const float*)d_in[0];
    const float* W0 = (const float*)d_in[1];
    const float* b0 = (const float*)d_in[2];
    const float* W1 = (const float*)d_in[3];
    const float* b1 = (const float*)d_in[4];
    const float* W2 = (const float*)d_in[5];
    const float* b2 = (const float*)d_in[6];
    float* out = (float*)d_out;

    __nv_bfloat16 *x0, *x1, *x2, *wext;
    char *spk, *wq;
    float* cur;
    cudaGetSymbolAddress((void**)&x0,  g_x0);
    cudaGetSymbolAddress((void**)&x1,  g_x1);
    cudaGetSymbolAddress((void**)&x2,  g_x2);
    cudaGetSymbolAddress((void**)&spk, g_spk);
    cudaGetSymbolAddress((void**)&cur, g_cur);
    cudaGetSymbolAddress((void**)&wext, g_wext);
    cudaGetSymbolAddress((void**)&wq,  g_wq);
    char* wq1 = wq;
    char* wq2 = wq + (size_t)H_ * KI8;

    cudaFuncSetAttribute(gemm_mma<512, 3>, cudaFuncAttributeMaxDynamicSharedMemorySize, SMEM_TOTAL);
    cudaFuncSetAttribute(gemm_i8, cudaFuncAttributeMaxDynamicSharedMemorySize, I8_SMEM);

    // prep
    prep_x_kernel<<<(M_ * D_ + 255) / 256, 256>>>(x);
    // layer0 pair sequence: A:{x0,x0,x1,x0,x1,x2}  W:{w0,w1,w0,w2,w1,w0}
    split_w_kernel<<<(H_ * D_ + 255) / 256, 256>>>(W0, wext, D_, 0, 1, 0, 2, 1, 0);
    quant_w_kernel<<<(H_ * H_ + 255) / 256, 256>>>(W1, wq1);
    quant_w_kernel<<<(H_ * H_ + 255) / 256, 256>>>(W2, wq2);

    // Layer 0 (bf16 3-plane path)
    {
        GemmArgs a;
        a.a[0] = x0; a.a[1] = x0; a.a[2] = x1; a.a[3] = x0; a.a[4] = x1; a.a[5] = x2;
        a.w = wext; a.bias = b0; a.c = cur;
        gemm_mma<512, 3><<<(M_ / 128) * (H_ / 256), 256, SMEM_TOTAL>>>(a);
    }
    scan_kernel<false><<<BH_ / 256, 256>>>(cur, spk, nullptr);

    // Layer 1 (int8 exact path)
    gemm_i8<<<(M_ / 128) * (H_ / 128), 256, I8_SMEM>>>(spk, wq1, b1, cur);
    scan_kernel<false><<<BH_ / 256, 256>>>(cur, spk, nullptr);

    // Layer 2 (int8 exact path)
    gemm_i8<<<(M_ / 128) * (H_ / 128), 256, I8_SMEM>>>(spk, wq2, b2, cur);
    scan_kernel<true><<<BH_ / 256, 256>>>(cur, nullptr, out);
}

// round 7
// speedup vs baseline: 3.4742x; 1.4624x over previous
#include <cuda_runtime.h>
#include <cstdint>
#include <cstddef>

#define T_  512
#define B_  32
#define D_  512
#define H_  1024
#define M_  (T_ * B_)      // 16384
#define BH_ (B_ * H_)      // 32768

#define KE0   3584         // layer0: 7 pairs x 512
#define NCH0  28
#define KE12  3072         // layers1,2: 3 planes x 1024
#define NCH12 24
#define MAXCH 28

#define I8_STAGE 32768     // A 128x128B + B 128x128B
#define I8_BIAS_OFF (3 * I8_STAGE)             // 98304
#define I8_SMEM (I8_BIAS_OFF + 512 + 128)

// ---------------- scratch (static device globals) ----------------
__device__ __align__(256) char g_xq[4][M_ * D_];   // x planes s8 [T,B,D]
__device__ __align__(256) char g_spk[M_ * H_];     // spikes s8 [T,B,H]
__device__ float g_cur[M_ * H_];                   // currents fp32 [T,B,H]
__device__ __align__(256) char g_we0[H_ * KE0];    // layer0 extended weights
__device__ __align__(256) char g_we12[2][H_ * KE12];

// ---------------- PTX helpers ----------------
__device__ __forceinline__ uint32_t smem_u32(const void* p) {
    uint32_t a;
    asm("{ .reg .u64 t; cvta.to.shared.u64 t, %1; cvt.u32.u64 %0, t; }" : "=r"(a) : "l"(p));
    return a;
}
__device__ __forceinline__ void cp_async16(uint32_t saddr, const void* gaddr) {
    asm volatile("cp.async.cg.shared.global [%0], [%1], 16;" :: "r"(saddr), "l"(gaddr) : "memory");
}
__device__ __forceinline__ void cp_commit() {
    asm volatile("cp.async.commit_group;" ::: "memory");
}
__device__ __forceinline__ void cp_wait1() {
    asm volatile("cp.async.wait_group 1;" ::: "memory");
}
__device__ __forceinline__ void cp_wait0() {
    asm volatile("cp.async.wait_group 0;" ::: "memory");
}
__device__ __forceinline__ void ldsm_x4(uint32_t* r, uint32_t addr) {
    asm volatile("ldmatrix.sync.aligned.m8n8.x4.shared.b16 {%0,%1,%2,%3}, [%4];"
                 : "=r"(r[0]), "=r"(r[1]), "=r"(r[2]), "=r"(r[3]) : "r"(addr));
}
__device__ __forceinline__ void imma16832(int* d, const uint32_t* a, uint32_t b0, uint32_t b1) {
    asm volatile(
        "mma.sync.aligned.m16n8k32.row.col.s32.s8.s8.s32 "
        "{%0,%1,%2,%3}, {%4,%5,%6,%7}, {%8,%9}, {%0,%1,%2,%3};"
        : "+r"(d[0]), "+r"(d[1]), "+r"(d[2]), "+r"(d[3])
        : "r"(a[0]), "r"(a[1]), "r"(a[2]), "r"(a[3]), "r"(b0), "r"(b1));
}

// ---------------- prep: transpose x + 4-plane radix-2^7 s8 split (Sx=16) ------
__global__ void quant_x_kernel(const float* __restrict__ x)
{
    int idx = blockIdx.x * blockDim.x + threadIdx.x;
    if (idx >= M_ * D_) return;
    int d  = idx % D_;
    int tb = idx / D_;
    int b  = tb % B_;
    int t  = tb / B_;
    float r = x[((size_t)b * T_ + t) * D_ + d] * 16.0f;   // exact
    #pragma unroll
    for (int g = 0; g < 4; g++) {
        float q = fminf(fmaxf(rintf(r), -127.0f), 127.0f);
        g_xq[g][idx] = (char)(int)q;
        r = (r - q) * 128.0f;                              // exact
    }
}

// ---------------- layer0 extended weights: 3 planes (Sw=2048), 7 pairs --------
__constant__ int c_wp0[7] = {0, 1, 0, 2, 1, 0, 0};
__global__ void quant_w0_kernel(const float* __restrict__ W)
{
    int idx = blockIdx.x * blockDim.x + threadIdx.x;
    if (idx >= H_ * D_) return;
    int n = idx / D_, k = idx % D_;
    float r = W[idx] * 2048.0f;
    char p[3];
    #pragma unroll
    for (int g = 0; g < 3; g++) {
        float q = fminf(fmaxf(rintf(r), -127.0f), 127.0f);
        p[g] = (char)(int)q;
        r = (r - q) * 128.0f;
    }
    #pragma unroll
    for (int pr = 0; pr < 7; pr++)
        g_we0[(size_t)n * KE0 + pr * D_ + k] = p[c_wp0[pr]];
}

// ---------------- layers1,2 weights: 3 planes (Sw=4096) -----------------------
__global__ void quant_w12_kernel(const float* __restrict__ W, char* __restrict__ dst)
{
    int idx = blockIdx.x * blockDim.x + threadIdx.x;
    if (idx >= H_ * H_) return;
    int n = idx / H_, k = idx % H_;
    float r = W[idx] * 4096.0f;
    #pragma unroll
    for (int g = 0; g < 3; g++) {
        float q = fminf(fmaxf(rintf(r), -127.0f), 127.0f);
        dst[(size_t)n * KE12 + (size_t)g * H_ + k] = (char)(int)q;
        r = (r - q) * 128.0f;
    }
}

// ---------------- unified int8 warp-IMMA GEMM ----------------
// C = sum over scale-groups( fold_scale * exact_s32_partial ) + bias
// CTA 128x128, 8 warps (2m x 4n), warp tile 64x32, BK=128 int8, 3-stage cp.async.
struct I8Args {
    const char* a_ptr[MAXCH];   // per-chunk A base (plane base + k offset)
    float       fold [MAXCH];   // 0 => no fold after this chunk
    const char* w;              // [H_, ke] extended weights
    const float* bias;
    float* c;
    int astride;                // A row stride (512 or 1024)
    int ke;                     // 3584 or 3072
    int nchunk;                 // 28 or 24
};

__global__ void __launch_bounds__(256, 1)
gemm_i8(I8Args args)
{
    extern __shared__ char smem[];
    const uint32_t sb = smem_u32(smem);
    const int tid  = threadIdx.x;
    const int wid  = tid >> 5;
    const int lane = tid & 31;

    const int tile_n = blockIdx.x & 7;         // H/128 = 8
    const int tile_m = blockIdx.x >> 3;        // M/128 = 128
    const int m0 = tile_m * 128;
    const int n0 = tile_n * 128;

    float* bias_s = (float*)(smem + I8_BIAS_OFF);
    if (tid < 128) bias_s[tid] = args.bias[n0 + tid];

    const int lrow = tid >> 3;                 // 0..31
    const int lc   = tid & 7;                  // 0..7
    const int nch  = args.nchunk;

    auto load_stage = [&](int ch, int s) {
        const char* Ap = args.a_ptr[ch];
        const uint32_t sa = sb + s * I8_STAGE;
        const uint32_t sB = sa + 16384;
        #pragma unroll
        for (int p = 0; p < 4; p++) {          // A: 128 rows x 128B
            const int row = lrow + 32 * p;
            const uint32_t dst = sa + (uint32_t)(row * 128 + ((lc ^ (row & 7)) * 16));
            cp_async16(dst, Ap + (size_t)(m0 + row) * args.astride + lc * 16);
        }
        #pragma unroll
        for (int p = 0; p < 4; p++) {          // B: 128 rows x 128B
            const int row = lrow + 32 * p;
            const uint32_t dst = sB + (uint32_t)(row * 128 + ((lc ^ (row & 7)) * 16));
            cp_async16(dst, args.w + (size_t)(n0 + row) * args.ke + (size_t)ch * 128 + lc * 16);
        }
        cp_commit();
    };

    float facc[4][4][4];
    int   iacc[4][4][4];
    #pragma unroll
    for (int i = 0; i < 4; i++)
        #pragma unroll
        for (int j = 0; j < 4; j++)
            #pragma unroll
            for (int e = 0; e < 4; e++) { facc[i][j][e] = 0.0f; iacc[i][j][e] = 0; }

    const int wm = (wid & 1) * 64;             // 2 warps over M
    const int wn = (wid >> 1) * 32;            // 4 warps over N

    load_stage(0, 0);
    load_stage(1, 1);

    #pragma unroll 1
    for (int ch = 0; ch < nch; ch++) {
        if (ch < nch - 1) cp_wait1(); else cp_wait0();
        __syncthreads();
        const int nc = ch + 2;
        if (nc < nch) load_stage(nc, nc % 3);

        const uint32_t sa = sb + (ch % 3) * I8_STAGE;
        const uint32_t sB = sa + 16384;

        #pragma unroll
        for (int k32 = 0; k32 < 4; k32++) {
            uint32_t ar[4][4];
            #pragma unroll
            for (int mt = 0; mt < 4; mt++) {
                const int row = wm + mt * 16 + (lane & 15);
                const int c   = 2 * k32 + (lane >> 4);
                ldsm_x4(ar[mt], sa + (uint32_t)(row * 128 + ((c ^ (row & 7)) * 16)));
            }
            uint32_t br[2][4];
            #pragma unroll
            for (int nt = 0; nt < 2; nt++) {
                const int row = wn + nt * 16 + (lane & 7) + (lane >> 4) * 8;
                const int c   = 2 * k32 + ((lane >> 3) & 1);
                ldsm_x4(br[nt], sB + (uint32_t)(row * 128 + ((c ^ (row & 7)) * 16)));
            }
            #pragma unroll
            for (int mt = 0; mt < 4; mt++)
                #pragma unroll
                for (int nt = 0; nt < 2; nt++) {
                    imma16832(iacc[mt][2 * nt],     ar[mt], br[nt][0], br[nt][1]);
                    imma16832(iacc[mt][2 * nt + 1], ar[mt], br[nt][2], br[nt][3]);
                }
        }

        const float fs = args.fold[ch];
        if (fs != 0.0f) {                      // exact power-of-2 scale fold
            #pragma unroll
            for (int mt = 0; mt < 4; mt++)
                #pragma unroll
                for (int j = 0; j < 4; j++)
                    #pragma unroll
                    for (int e = 0; e < 4; e++) {
                        facc[mt][j][e] += (float)iacc[mt][j][e] * fs;
                        iacc[mt][j][e] = 0;
                    }
        }
    }
    __syncthreads();

    // epilogue: facc -> smem -> coalesced stores (+bias)
    float* stg = (float*)smem;                 // 128 x 132 floats
    #pragma unroll
    for (int mt = 0; mt < 4; mt++) {
        #pragma unroll
        for (int j = 0; j < 4; j++) {
            const int r0 = wm + mt * 16 + lane / 4;
            const int cc = wn + j * 8 + 2 * (lane % 4);
            stg[r0 * 132 + cc]           = facc[mt][j][0];
            stg[r0 * 132 + cc + 1]       = facc[mt][j][1];
            stg[(r0 + 8) * 132 + cc]     = facc[mt][j][2];
            stg[(r0 + 8) * 132 + cc + 1] = facc[mt][j][3];
        }
    }
    __syncthreads();
    #pragma unroll 4
    for (int it = 0; it < 16; it++) {
        const int idx = it * 1024 + tid * 4;
        const int row = idx >> 7, col = idx & 127;
        float4 v = *(const float4*)&stg[row * 132 + col];
        v.x += bias_s[col];
        v.y += bias_s[col + 1];
        v.z += bias_s[col + 2];
        v.w += bias_s[col + 3];
        *(float4*)&args.c[(size_t)(m0 + row) * H_ + n0 + col] = v;
    }
}

// ---------------- serial LIF scan ----------------
template<bool FINAL_OUT>
__global__ void scan_kernel(const float* __restrict__ I,
                            char* __restrict__ Sb,
                            float* __restrict__ Of)
{
    int idx = blockIdx.x * blockDim.x + threadIdx.x;
    if (idx >= BH_) return;
    const int b = idx / H_;
    const int h = idx % H_;
    float u = 0.0f;
    #pragma unroll 16
    for (int t = 0; t < T_; t++) {
        float cur = I[(size_t)t * BH_ + idx];
        u = 0.5f * u + cur;
        float v = u - 0.5f;
        bool fire = (v >= 0.0f);
        if (FINAL_OUT) Of[((size_t)b * T_ + t) * H_ + h] = fire ? 1.0f : 0.0f;
        else           Sb[(size_t)t * BH_ + idx] = fire ? 1 : 0;
        u = fire ? 0.0f : u;
    }
}

// ---------------- launch ----------------
extern "C" void kernel_launch(void* const* d_in, const int* in_sizes, int n_in,
                              void* d_out, int out_size)
{
    const float* x  = (const float*)d_in[0];
    const float* W0 = (const float*)d_in[1];
    const float* b0 = (const float*)d_in[2];
    const float* W1 = (const float*)d_in[3];
    const float* b1 = (const float*)d_in[4];
    const float* W2 = (const float*)d_in[5];
    const float* b2 = (const float*)d_in[6];
    float* out = (float*)d_out;

    char *xq, *spk, *we0, *we12;
    float* cur;
    cudaGetSymbolAddress((void**)&xq,   g_xq);
    cudaGetSymbolAddress((void**)&spk,  g_spk);
    cudaGetSymbolAddress((void**)&cur,  g_cur);
    cudaGetSymbolAddress((void**)&we0,  g_we0);
    cudaGetSymbolAddress((void**)&we12, g_we12);
    char* we1 = we12;
    char* we2 = we12 + (size_t)H_ * KE12;

    cudaFuncSetAttribute(gemm_i8, cudaFuncAttributeMaxDynamicSharedMemorySize, I8_SMEM);

    // prep
    quant_x_kernel  <<<(M_ * D_ + 255) / 256, 256>>>(x);
    quant_w0_kernel <<<(H_ * D_ + 255) / 256, 256>>>(W0);
    quant_w12_kernel<<<(H_ * H_ + 255) / 256, 256>>>(W1, we1);
    quant_w12_kernel<<<(H_ * H_ + 255) / 256, 256>>>(W2, we2);

    const int GRID = (M_ / 128) * (H_ / 128);   // 1024 CTAs

    // Layer 0: pairs (x_i, w_j): p=0..6 -> x planes {0,0,1,0,1,2,3}
    // scale groups by s=i+j: {0 | 1,1 | 2,2,2 | 3}; Sx*Sw = 2^15.
    {
        I8Args a = {};
        const int xp[7] = {0, 0, 1, 0, 1, 2, 3};
        for (int ch = 0; ch < NCH0; ch++) {
            int p = ch >> 2;
            a.a_ptr[ch] = xq + (size_t)xp[p] * (M_ * D_) + (ch & 3) * 128;
            a.fold[ch] = 0.0f;
        }
        a.fold[3]  = 3.0517578125e-05f;        // 2^-15
        a.fold[11] = 2.384185791015625e-07f;   // 2^-22
        a.fold[23] = 1.862645149230957e-09f;   // 2^-29
        a.fold[27] = 1.4551915228366852e-11f;  // 2^-36
        a.w = we0; a.bias = b0; a.c = cur;
        a.astride = D_; a.ke = KE0; a.nchunk = NCH0;
        gemm_i8<<<GRID, 256, I8_SMEM>>>(a);
    }
    scan_kernel<false><<<BH_ / 256, 256>>>(cur, spk, nullptr);

    // Layers 1 & 2: 3 weight planes, Sw = 2^12.
    for (int layer = 1; layer <= 2; layer++) {
        I8Args a = {};
        for (int ch = 0; ch < NCH12; ch++) {
            a.a_ptr[ch] = spk + (ch & 7) * 128;
            a.fold[ch] = 0.0f;
        }
        a.fold[7]  = 2.44140625e-04f;          // 2^-12
        a.fold[15] = 1.9073486328125e-06f;     // 2^-19
        a.fold[23] = 1.4901161193847656e-08f;  // 2^-26
        a.w = (layer == 1) ? we1 : we2;
        a.bias = (layer == 1) ? b1 : b2;
        a.c = cur;
        a.astride = H_; a.ke = KE12; a.nchunk = NCH12;
        gemm_i8<<<GRID, 256, I8_SMEM>>>(a);
        if (layer == 1) scan_kernel<false><<<BH_ / 256, 256>>>(cur, spk, nullptr);
        else            scan_kernel<true> <<<BH_ / 256, 256>>>(cur, nullptr, out);
    }
}